// round 14
// baseline (speedup 1.0000x reference)
#include <cuda_runtime.h>
#include <cstdint>

// CIN forward via warp-level TF32 mma.sync (m16n8k8), 3 fused GEMM layers.
// Layer 0 symmetric-folded (K0=780 -> 25 chunks). B frags in registers,
// prefetched one chunk ahead. A double-buffered in smem, packed-f32x2 fill
// with exact tf32-rna (+magic). R11: x-operand hoisted (f const per chunk,
// layers 1-2) and xs/hs stride 65->68 float2 (h-gather conflicts 4->2 way).

#define NCH0 25
#define NCH12 78
#define NCHT 181
#define HST 68   // float2 stride of xs2/hs2 rows

__device__ __align__(16) float g_wt[(size_t)(NCHT + 1) * 4096];

#define SM_OSUM 0         // 2048 f
#define SM_BIAS 8192      // 384 f
#define SM_LUT  9728      // 800 u32
#define SM_XS   12928     // 39*68 float2 = 21216 B
#define SM_HS   34144     // 64*68 float2 = 34816 B
#define SM_A0   68960     // 16 KB
#define SM_A1   85344     // 16 KB
#define SM_TOT  101728

#define MAGIC 0x0000100000001000ULL

__device__ __forceinline__ float tf32r(float v) {
    uint32_t r; asm("cvt.rna.tf32.f32 %0, %1;" : "=r"(r) : "f"(v));
    return __uint_as_float(r);
}
__device__ __forceinline__ unsigned long long mul2u(unsigned long long a,
                                                    unsigned long long b) {
    unsigned long long r;
    asm("mul.rn.f32x2 %0, %1, %2;" : "=l"(r) : "l"(a), "l"(b));
    return r;
}
__device__ __forceinline__ void mma8v(float* c, uint4 a, uint32_t b0, uint32_t b1) {
    asm volatile("mma.sync.aligned.m16n8k8.row.col.f32.tf32.tf32.f32 "
        "{%0,%1,%2,%3}, {%4,%5,%6,%7}, {%8,%9}, {%0,%1,%2,%3};"
        : "+f"(c[0]), "+f"(c[1]), "+f"(c[2]), "+f"(c[3])
        : "r"(a.x), "r"(a.y), "r"(a.z), "r"(a.w), "r"(b0), "r"(b1));
}

// ---- W prep: fragment order rem = ((kp*16+ntile)*32+lane)*4 + r ----
__global__ void wt_prep0(const float* __restrict__ W) {   // layer 0, symmetric fold
    int idx = blockIdx.x * 256 + threadIdx.x;
    if (idx >= NCH0 * 4096) return;
    int cl = idx >> 12, rem = idx & 4095;
    int r = rem & 3, lane = (rem >> 2) & 31, ntile = (rem >> 7) & 15, kp = rem >> 11;
    int ks = kp * 2 + (r >> 1), reg = r & 1;
    int n = ntile * 8 + (lane >> 2);
    int k = cl * 32 + ks * 8 + (lane & 3) + reg * 4;
    float v = 0.0f;
    if (k < 780) {
        int f = 0, s = 0;
        while (s + (39 - f) <= k) { s += 39 - f; ++f; }
        int g = f + (k - s);
        v = W[(size_t)(f * 39 + g) * 128 + n];
        if (g != f) v += W[(size_t)(g * 39 + f) * 128 + n];
    }
    g_wt[(size_t)cl * 4096 + rem] = tf32r(v);
}
__global__ void wt_prep(const float* __restrict__ W, int K, int chunk0, int nchunks) {
    int idx = blockIdx.x * 256 + threadIdx.x;
    if (idx >= nchunks * 4096) return;
    int cl = idx >> 12, rem = idx & 4095;
    int r = rem & 3, lane = (rem >> 2) & 31, ntile = (rem >> 7) & 15, kp = rem >> 11;
    int ks = kp * 2 + (r >> 1), reg = r & 1;
    int n = ntile * 8 + (lane >> 2);
    int k = cl * 32 + ks * 8 + (lane & 3) + reg * 4;
    float v = (k < K) ? W[(size_t)k * 128 + n] : 0.0f;
    g_wt[(size_t)(chunk0 + cl) * 4096 + rem] = tf32r(v);
}

// ---- fill slots ----
// Layer 0 (LUT, x==h):
__device__ __forceinline__ void fill_slot0(
    ulonglong2* __restrict__ adst, int tid, int icb, int c, int j,
    const unsigned long long* __restrict__ xrow, const uint32_t* __restrict__ lut)
{
    int k = icb + j * 8 + c;
    uint32_t u0 = lut[k], u1 = lut[k + 4];
    int f0 = u0 & 255, g0 = u0 >> 8;
    int f1 = u1 & 255, g1 = u1 >> 8;
    ulonglong2 o;
    o.x = mul2u(xrow[f0 * HST], xrow[g0 * HST]) + MAGIC;
    o.y = mul2u(xrow[f1 * HST], xrow[g1 * HST]) + MAGIC;
    adst[tid + 256 * j] = o;
}
// Layers 1-2 (f constant per chunk; xv preloaded; hgb = hrow + (icb&63)*HST):
__device__ __forceinline__ void fill_slot12(
    ulonglong2* __restrict__ adst, int tid, int c, int j,
    unsigned long long xv, const unsigned long long* __restrict__ hgb)
{
    int g = j * 8 + c;
    ulonglong2 o;
    o.x = mul2u(xv, hgb[g * HST]) + MAGIC;
    o.y = mul2u(xv, hgb[(g + 4) * HST]) + MAGIC;
    adst[tid + 256 * j] = o;
}

__device__ __forceinline__ void ldB4(uint4* b, const uint4* __restrict__ p) {
    #pragma unroll
    for (int nt = 0; nt < 4; ++nt) b[nt] = __ldg(p + nt * 32);
}

// Chunk body: MMA(ic), fill(ic+1) slots + B prefetch interleaved per ks.
template <int L0>
__device__ __forceinline__ void chunk_body(
    const uint4* __restrict__ ap, ulonglong2* __restrict__ an,
    float acc[4][4][4], uint4* bcur, const uint4* __restrict__ bnext,
    int dofill, int tid, int icb, int c,
    const unsigned long long* __restrict__ xrow,
    unsigned long long xv, const unsigned long long* __restrict__ hgb,
    const uint32_t* __restrict__ lut)
{
    #pragma unroll
    for (int ks = 0; ks < 4; ++ks) {
        const int kp = ks >> 1, k2 = ks & 1;
        #pragma unroll
        for (int mt = 0; mt < 4; ++mt) {
            uint4 av = ap[ks * 256 + mt * 32];
            #pragma unroll
            for (int nt = 0; nt < 4; ++nt)
                mma8v(acc[mt][nt], av,
                      k2 ? bcur[kp * 4 + nt].z : bcur[kp * 4 + nt].x,
                      k2 ? bcur[kp * 4 + nt].w : bcur[kp * 4 + nt].y);
        }
        if (dofill) {
            if (L0) fill_slot0(an, tid, icb, c, ks, xrow, lut);
            else    fill_slot12(an, tid, c, ks, xv, hgb);
        }
        if (ks == 1) ldB4(bcur, bnext);
        if (ks == 3) ldB4(bcur + 4, bnext + 512);
    }
}

__global__ void __launch_bounds__(256, 2) cin_mma_kernel(
    const float* __restrict__ x,
    const float* __restrict__ b0, const float* __restrict__ b1,
    const float* __restrict__ b2,
    float* __restrict__ out)
{
    extern __shared__ char smem[];
    float*    osum   = (float*)(smem + SM_OSUM);
    float*    bias_s = (float*)(smem + SM_BIAS);
    uint32_t* lut    = (uint32_t*)(smem + SM_LUT);
    float2*   xs2    = (float2*)(smem + SM_XS);   // [f][col], stride HST
    float2*   hs2    = (float2*)(smem + SM_HS);   // [g][col], stride HST

    const int tid = threadIdx.x, lane = tid & 31, wid = tid >> 5;
    const int pair0 = blockIdx.x * 128;
    const int wm = wid & 1, wn = wid >> 1;
    const int c = lane & 3;
    const int colid = wid * 8 + (lane >> 2);

    for (int i = tid; i < 2048; i += 256) osum[i] = 0.0f;
    for (int i = tid; i < 128 * 39; i += 256) {
        int m = i & 127, f = i >> 7, pr = pair0 + m;
        float v = x[((size_t)(pr >> 4) * 39 + f) * 16 + (pr & 15)];
        ((float*)xs2)[(f * HST + (m >> 4) * 8 + (m & 7)) * 2 + ((m >> 3) & 1)] = v;
    }
    for (int i = tid; i < 384; i += 256) {
        const float* bp = (i < 128) ? b0 : ((i < 256) ? b1 : b2);
        bias_s[i] = bp[i & 127];
    }
    for (int k = tid; k < 800; k += 256) {
        int f = 0, s = 0, g = 0;
        if (k < 780) {
            while (s + (39 - f) <= k) { s += 39 - f; ++f; }
            g = f + (k - s);
        } else f = 0;
        lut[k] = (uint32_t)f | ((uint32_t)g << 8);
    }

    float acc[4][4][4];
    #pragma unroll
    for (int a = 0; a < 4; ++a)
        #pragma unroll
        for (int b = 0; b < 4; ++b)
            #pragma unroll
            for (int cc = 0; cc < 4; ++cc) acc[a][b][cc] = 0.0f;

    ulonglong2* a0 = (ulonglong2*)(smem + SM_A0);
    ulonglong2* a1 = (ulonglong2*)(smem + SM_A1);
    const uint4* bptr = (const uint4*)g_wt + (wn * 128 + lane);
    uint4 bcur[8];
    ldB4(bcur, bptr); ldB4(bcur + 4, bptr + 512);
    int pb = 0;

    const unsigned long long* xrow = (const unsigned long long*)(xs2 + colid);

    for (int layer = 0; layer < 3; ++layer) {
        const int nck = (layer == 0) ? NCH0 : NCH12;
        const unsigned long long* hrow =
            (const unsigned long long*)(((layer == 0) ? xs2 : hs2) + colid);

        __syncthreads();                          // xs2/hs2/lut writes visible
        {   // prologue fill of chunk 0
            ulonglong2* an = pb ? a1 : a0;
            if (layer == 0) {
                #pragma unroll
                for (int j = 0; j < 4; ++j) fill_slot0(an, tid, 0, c, j, xrow, lut);
            } else {
                unsigned long long xv = xrow[0];
                #pragma unroll
                for (int j = 0; j < 4; ++j) fill_slot12(an, tid, c, j, xv, hrow);
            }
        }

        for (int ic = 0; ic < nck; ++ic) {
            __syncthreads();                      // fill(ic) visible; abuf[pb^1] free
            const uint4* ap = (pb ? (const uint4*)a1 : (const uint4*)a0) + (wm * 128 + lane);
            ulonglong2* an = pb ? a0 : a1;
            const int dofill = (ic + 1 < nck);
            const int icb = (ic + 1) * 32;
            if (layer == 0) {
                chunk_body<1>(ap, an, acc, bcur, bptr + 1024, dofill, tid,
                              icb, c, xrow, 0ull, hrow, lut);
            } else {
                unsigned long long xv = dofill ? xrow[(icb >> 6) * HST] : 0ull;
                const unsigned long long* hgb = hrow + (icb & 63) * HST;
                chunk_body<0>(ap, an, acc, bcur, bptr + 1024, dofill, tid,
                              icb, c, xrow, xv, hgb, lut);
            }
            bptr += 1024;
            pb ^= 1;
        }

        // ---- epilogue: bias + relu, h pairs for next layer, d-sum ----
        #pragma unroll
        for (int mt = 0; mt < 4; ++mt) {
            int b_loc = wm * 4 + mt;
            int hcol = (wm * 4 + mt) * 8 + (lane >> 2);
            #pragma unroll
            for (int nt = 0; nt < 4; ++nt) {
                int n = wn * 32 + nt * 8 + (lane & 3) * 2;
                float bi0 = bias_s[layer * 128 + n];
                float bi1 = bias_s[layer * 128 + n + 1];
                float v0 = fmaxf(acc[mt][nt][0] + bi0, 0.0f);
                float v1 = fmaxf(acc[mt][nt][1] + bi1, 0.0f);
                float v2 = fmaxf(acc[mt][nt][2] + bi0, 0.0f);
                float v3 = fmaxf(acc[mt][nt][3] + bi1, 0.0f);
                acc[mt][nt][0] = 0.0f; acc[mt][nt][1] = 0.0f;
                acc[mt][nt][2] = 0.0f; acc[mt][nt][3] = 0.0f;
                if (layer < 2 && n < 64) {
                    hs2[n * HST + hcol]       = make_float2(v0, v2);
                    hs2[(n + 1) * HST + hcol] = make_float2(v1, v3);
                }
                int ch = (layer == 0) ? (n >= 64 ? n - 64 : -1)
                       : (layer == 1) ? (n >= 64 ? n : -1)
                       : (128 + n);
                if (ch >= 0) {
                    atomicAdd(&osum[b_loc * 256 + ch],     v0 + v2);
                    atomicAdd(&osum[b_loc * 256 + ch + 1], v1 + v3);
                }
            }
        }
    }

    __syncthreads();
    const int bbase = blockIdx.x * 8;
    for (int i = tid; i < 2048; i += 256)
        out[(size_t)(bbase + (i >> 8)) * 256 + (i & 255)] = osum[i];
}

extern "C" void kernel_launch(void* const* d_in, const int* in_sizes, int n_in,
                              void* d_out, int out_size) {
    const float* x  = (const float*)d_in[0];
    const float* W0 = (const float*)d_in[1];
    const float* W1 = (const float*)d_in[2];
    const float* W2 = (const float*)d_in[3];
    const float* b0 = (const float*)d_in[4];
    const float* b1 = (const float*)d_in[5];
    const float* b2 = (const float*)d_in[6];
    float* out = (float*)d_out;

    wt_prep0<<<NCH0 * 16, 256>>>(W0);
    wt_prep<<<NCH12 * 16, 256>>>(W1, 2496, NCH0, NCH12);
    wt_prep<<<NCH12 * 16, 256>>>(W2, 2496, NCH0 + NCH12, NCH12);

    cudaFuncSetAttribute(cin_mma_kernel, cudaFuncAttributeMaxDynamicSharedMemorySize, SM_TOT);
    cin_mma_kernel<<<256, 256, SM_TOT>>>(x, b0, b1, b2, out);
}

// round 15
// speedup vs baseline: 1.0010x; 1.0010x over previous
#include <cuda_runtime.h>
#include <cstdint>

// CIN forward via warp-level TF32 mma.sync (m16n8k8), 3 fused GEMM layers.
// Layer 0 symmetric-folded (K0=780 -> 25 chunks). B frags in registers,
// prefetched one chunk ahead. A double-buffered in smem, packed-f32x2 fill
// with exact tf32-rna (+magic). R11: x-operand hoisted (f const per chunk,
// layers 1-2) and xs/hs stride 65->68 float2 (h-gather conflicts 4->2 way).

#define NCH0 25
#define NCH12 78
#define NCHT 181
#define HST 68   // float2 stride of xs2/hs2 rows

__device__ __align__(16) float g_wt[(size_t)(NCHT + 1) * 4096];

#define SM_OSUM 0         // 2048 f
#define SM_BIAS 8192      // 384 f
#define SM_LUT  9728      // 800 u32
#define SM_XS   12928     // 39*68 float2 = 21216 B
#define SM_HS   34144     // 64*68 float2 = 34816 B
#define SM_A0   68960     // 16 KB
#define SM_A1   85344     // 16 KB
#define SM_TOT  101728

#define MAGIC 0x0000100000001000ULL

__device__ __forceinline__ float tf32r(float v) {
    uint32_t r; asm("cvt.rna.tf32.f32 %0, %1;" : "=r"(r) : "f"(v));
    return __uint_as_float(r);
}
__device__ __forceinline__ unsigned long long mul2u(unsigned long long a,
                                                    unsigned long long b) {
    unsigned long long r;
    asm("mul.rn.f32x2 %0, %1, %2;" : "=l"(r) : "l"(a), "l"(b));
    return r;
}
__device__ __forceinline__ void mma8v(float* c, uint4 a, uint32_t b0, uint32_t b1) {
    asm volatile("mma.sync.aligned.m16n8k8.row.col.f32.tf32.tf32.f32 "
        "{%0,%1,%2,%3}, {%4,%5,%6,%7}, {%8,%9}, {%0,%1,%2,%3};"
        : "+f"(c[0]), "+f"(c[1]), "+f"(c[2]), "+f"(c[3])
        : "r"(a.x), "r"(a.y), "r"(a.z), "r"(a.w), "r"(b0), "r"(b1));
}

// ---- W prep: fragment order rem = ((kp*16+ntile)*32+lane)*4 + r ----
__global__ void wt_prep0(const float* __restrict__ W) {   // layer 0, symmetric fold
    int idx = blockIdx.x * 256 + threadIdx.x;
    if (idx >= NCH0 * 4096) return;
    int cl = idx >> 12, rem = idx & 4095;
    int r = rem & 3, lane = (rem >> 2) & 31, ntile = (rem >> 7) & 15, kp = rem >> 11;
    int ks = kp * 2 + (r >> 1), reg = r & 1;
    int n = ntile * 8 + (lane >> 2);
    int k = cl * 32 + ks * 8 + (lane & 3) + reg * 4;
    float v = 0.0f;
    if (k < 780) {
        int f = 0, s = 0;
        while (s + (39 - f) <= k) { s += 39 - f; ++f; }
        int g = f + (k - s);
        v = W[(size_t)(f * 39 + g) * 128 + n];
        if (g != f) v += W[(size_t)(g * 39 + f) * 128 + n];
    }
    g_wt[(size_t)cl * 4096 + rem] = tf32r(v);
}
__global__ void wt_prep(const float* __restrict__ W, int K, int chunk0, int nchunks) {
    int idx = blockIdx.x * 256 + threadIdx.x;
    if (idx >= nchunks * 4096) return;
    int cl = idx >> 12, rem = idx & 4095;
    int r = rem & 3, lane = (rem >> 2) & 31, ntile = (rem >> 7) & 15, kp = rem >> 11;
    int ks = kp * 2 + (r >> 1), reg = r & 1;
    int n = ntile * 8 + (lane >> 2);
    int k = cl * 32 + ks * 8 + (lane & 3) + reg * 4;
    float v = (k < K) ? W[(size_t)k * 128 + n] : 0.0f;
    g_wt[(size_t)(chunk0 + cl) * 4096 + rem] = tf32r(v);
}

// ---- fill slots ----
// Layer 0 (LUT, x==h):
__device__ __forceinline__ void fill_slot0(
    ulonglong2* __restrict__ adst, int tid, int icb, int c, int j,
    const unsigned long long* __restrict__ xrow, const uint32_t* __restrict__ lut)
{
    int k = icb + j * 8 + c;
    uint32_t u0 = lut[k], u1 = lut[k + 4];
    int f0 = u0 & 255, g0 = u0 >> 8;
    int f1 = u1 & 255, g1 = u1 >> 8;
    ulonglong2 o;
    o.x = mul2u(xrow[f0 * HST], xrow[g0 * HST]) + MAGIC;
    o.y = mul2u(xrow[f1 * HST], xrow[g1 * HST]) + MAGIC;
    adst[tid + 256 * j] = o;
}
// Layers 1-2 (f constant per chunk; xv preloaded; hgb = hrow + (icb&63)*HST):
__device__ __forceinline__ void fill_slot12(
    ulonglong2* __restrict__ adst, int tid, int c, int j,
    unsigned long long xv, const unsigned long long* __restrict__ hgb)
{
    int g = j * 8 + c;
    ulonglong2 o;
    o.x = mul2u(xv, hgb[g * HST]) + MAGIC;
    o.y = mul2u(xv, hgb[(g + 4) * HST]) + MAGIC;
    adst[tid + 256 * j] = o;
}

__device__ __forceinline__ void ldB4(uint4* b, const uint4* __restrict__ p) {
    #pragma unroll
    for (int nt = 0; nt < 4; ++nt) b[nt] = __ldg(p + nt * 32);
}

// Chunk body: MMA(ic), fill(ic+1) slots + B prefetch interleaved per ks.
template <int L0>
__device__ __forceinline__ void chunk_body(
    const uint4* __restrict__ ap, ulonglong2* __restrict__ an,
    float acc[4][4][4], uint4* bcur, const uint4* __restrict__ bnext,
    int dofill, int tid, int icb, int c,
    const unsigned long long* __restrict__ xrow,
    unsigned long long xv, const unsigned long long* __restrict__ hgb,
    const uint32_t* __restrict__ lut)
{
    #pragma unroll
    for (int ks = 0; ks < 4; ++ks) {
        const int kp = ks >> 1, k2 = ks & 1;
        #pragma unroll
        for (int mt = 0; mt < 4; ++mt) {
            uint4 av = ap[ks * 256 + mt * 32];
            #pragma unroll
            for (int nt = 0; nt < 4; ++nt)
                mma8v(acc[mt][nt], av,
                      k2 ? bcur[kp * 4 + nt].z : bcur[kp * 4 + nt].x,
                      k2 ? bcur[kp * 4 + nt].w : bcur[kp * 4 + nt].y);
        }
        if (dofill) {
            if (L0) fill_slot0(an, tid, icb, c, ks, xrow, lut);
            else    fill_slot12(an, tid, c, ks, xv, hgb);
        }
        if (ks == 1) ldB4(bcur, bnext);
        if (ks == 3) ldB4(bcur + 4, bnext + 512);
    }
}

__global__ void __launch_bounds__(256, 2) cin_mma_kernel(
    const float* __restrict__ x,
    const float* __restrict__ b0, const float* __restrict__ b1,
    const float* __restrict__ b2,
    float* __restrict__ out)
{
    extern __shared__ char smem[];
    float*    osum   = (float*)(smem + SM_OSUM);
    float*    bias_s = (float*)(smem + SM_BIAS);
    uint32_t* lut    = (uint32_t*)(smem + SM_LUT);
    float2*   xs2    = (float2*)(smem + SM_XS);   // [f][col], stride HST
    float2*   hs2    = (float2*)(smem + SM_HS);   // [g][col], stride HST

    const int tid = threadIdx.x, lane = tid & 31, wid = tid >> 5;
    const int pair0 = blockIdx.x * 128;
    const int wm = wid & 1, wn = wid >> 1;
    const int c = lane & 3;
    const int colid = wid * 8 + (lane >> 2);

    for (int i = tid; i < 2048; i += 256) osum[i] = 0.0f;
    for (int i = tid; i < 128 * 39; i += 256) {
        int m = i & 127, f = i >> 7, pr = pair0 + m;
        float v = x[((size_t)(pr >> 4) * 39 + f) * 16 + (pr & 15)];
        ((float*)xs2)[(f * HST + (m >> 4) * 8 + (m & 7)) * 2 + ((m >> 3) & 1)] = v;
    }
    for (int i = tid; i < 384; i += 256) {
        const float* bp = (i < 128) ? b0 : ((i < 256) ? b1 : b2);
        bias_s[i] = bp[i & 127];
    }
    for (int k = tid; k < 800; k += 256) {
        int f = 0, s = 0, g = 0;
        if (k < 780) {
            while (s + (39 - f) <= k) { s += 39 - f; ++f; }
            g = f + (k - s);
        } else f = 0;
        lut[k] = (uint32_t)f | ((uint32_t)g << 8);
    }

    float acc[4][4][4];
    #pragma unroll
    for (int a = 0; a < 4; ++a)
        #pragma unroll
        for (int b = 0; b < 4; ++b)
            #pragma unroll
            for (int cc = 0; cc < 4; ++cc) acc[a][b][cc] = 0.0f;

    ulonglong2* a0 = (ulonglong2*)(smem + SM_A0);
    ulonglong2* a1 = (ulonglong2*)(smem + SM_A1);
    const uint4* bptr = (const uint4*)g_wt + (wn * 128 + lane);
    uint4 bcur[8];
    ldB4(bcur, bptr); ldB4(bcur + 4, bptr + 512);
    int pb = 0;

    const unsigned long long* xrow = (const unsigned long long*)(xs2 + colid);

    for (int layer = 0; layer < 3; ++layer) {
        const int nck = (layer == 0) ? NCH0 : NCH12;
        const unsigned long long* hrow =
            (const unsigned long long*)(((layer == 0) ? xs2 : hs2) + colid);

        __syncthreads();                          // xs2/hs2/lut writes visible
        {   // prologue fill of chunk 0
            ulonglong2* an = pb ? a1 : a0;
            if (layer == 0) {
                #pragma unroll
                for (int j = 0; j < 4; ++j) fill_slot0(an, tid, 0, c, j, xrow, lut);
            } else {
                unsigned long long xv = xrow[0];
                #pragma unroll
                for (int j = 0; j < 4; ++j) fill_slot12(an, tid, c, j, xv, hrow);
            }
        }

        for (int ic = 0; ic < nck; ++ic) {
            __syncthreads();                      // fill(ic) visible; abuf[pb^1] free
            const uint4* ap = (pb ? (const uint4*)a1 : (const uint4*)a0) + (wm * 128 + lane);
            ulonglong2* an = pb ? a0 : a1;
            const int dofill = (ic + 1 < nck);
            const int icb = (ic + 1) * 32;
            if (layer == 0) {
                chunk_body<1>(ap, an, acc, bcur, bptr + 1024, dofill, tid,
                              icb, c, xrow, 0ull, hrow, lut);
            } else {
                unsigned long long xv = dofill ? xrow[(icb >> 6) * HST] : 0ull;
                const unsigned long long* hgb = hrow + (icb & 63) * HST;
                chunk_body<0>(ap, an, acc, bcur, bptr + 1024, dofill, tid,
                              icb, c, xrow, xv, hgb, lut);
            }
            bptr += 1024;
            pb ^= 1;
        }

        // ---- epilogue: bias + relu, h pairs for next layer, d-sum ----
        #pragma unroll
        for (int mt = 0; mt < 4; ++mt) {
            int b_loc = wm * 4 + mt;
            int hcol = (wm * 4 + mt) * 8 + (lane >> 2);
            #pragma unroll
            for (int nt = 0; nt < 4; ++nt) {
                int n = wn * 32 + nt * 8 + (lane & 3) * 2;
                float bi0 = bias_s[layer * 128 + n];
                float bi1 = bias_s[layer * 128 + n + 1];
                float v0 = fmaxf(acc[mt][nt][0] + bi0, 0.0f);
                float v1 = fmaxf(acc[mt][nt][1] + bi1, 0.0f);
                float v2 = fmaxf(acc[mt][nt][2] + bi0, 0.0f);
                float v3 = fmaxf(acc[mt][nt][3] + bi1, 0.0f);
                acc[mt][nt][0] = 0.0f; acc[mt][nt][1] = 0.0f;
                acc[mt][nt][2] = 0.0f; acc[mt][nt][3] = 0.0f;
                if (layer < 2 && n < 64) {
                    hs2[n * HST + hcol]       = make_float2(v0, v2);
                    hs2[(n + 1) * HST + hcol] = make_float2(v1, v3);
                }
                int ch = (layer == 0) ? (n >= 64 ? n - 64 : -1)
                       : (layer == 1) ? (n >= 64 ? n : -1)
                       : (128 + n);
                if (ch >= 0) {
                    atomicAdd(&osum[b_loc * 256 + ch],     v0 + v2);
                    atomicAdd(&osum[b_loc * 256 + ch + 1], v1 + v3);
                }
            }
        }
    }

    __syncthreads();
    const int bbase = blockIdx.x * 8;
    for (int i = tid; i < 2048; i += 256)
        out[(size_t)(bbase + (i >> 8)) * 256 + (i & 255)] = osum[i];
}

extern "C" void kernel_launch(void* const* d_in, const int* in_sizes, int n_in,
                              void* d_out, int out_size) {
    const float* x  = (const float*)d_in[0];
    const float* W0 = (const float*)d_in[1];
    const float* W1 = (const float*)d_in[2];
    const float* W2 = (const float*)d_in[3];
    const float* b0 = (const float*)d_in[4];
    const float* b1 = (const float*)d_in[5];
    const float* b2 = (const float*)d_in[6];
    float* out = (float*)d_out;

    wt_prep0<<<NCH0 * 16, 256>>>(W0);
    wt_prep<<<NCH12 * 16, 256>>>(W1, 2496, NCH0, NCH12);
    wt_prep<<<NCH12 * 16, 256>>>(W2, 2496, NCH0 + NCH12, NCH12);

    cudaFuncSetAttribute(cin_mma_kernel, cudaFuncAttributeMaxDynamicSharedMemorySize, SM_TOT);
    cin_mma_kernel<<<256, 256, SM_TOT>>>(x, b0, b1, b2, out);
}

// round 16
// speedup vs baseline: 1.0036x; 1.0026x over previous
#include <cuda_runtime.h>
#include <cstdint>

// CIN forward via warp-level TF32 mma.sync (m16n8k8), 3 fused GEMM layers.
// Layer 0 symmetric-folded (K0=780 -> 25 chunks). B frags in registers,
// prefetched one chunk ahead. A double-buffered in smem, packed-f32x2 fill
// with exact tf32-rna (+magic). R11: x-operand hoisted (f const per chunk,
// layers 1-2) and xs/hs stride 65->68 float2 (h-gather conflicts 4->2 way).

#define NCH0 25
#define NCH12 78
#define NCHT 181
#define HST 68   // float2 stride of xs2/hs2 rows

__device__ __align__(16) float g_wt[(size_t)(NCHT + 1) * 4096];

#define SM_OSUM 0         // 2048 f
#define SM_BIAS 8192      // 384 f
#define SM_LUT  9728      // 800 u32
#define SM_XS   12928     // 39*68 float2 = 21216 B
#define SM_HS   34144     // 64*68 float2 = 34816 B
#define SM_A0   68960     // 16 KB
#define SM_A1   85344     // 16 KB
#define SM_TOT  101728

#define MAGIC 0x0000100000001000ULL

__device__ __forceinline__ float tf32r(float v) {
    uint32_t r; asm("cvt.rna.tf32.f32 %0, %1;" : "=r"(r) : "f"(v));
    return __uint_as_float(r);
}
__device__ __forceinline__ unsigned long long mul2u(unsigned long long a,
                                                    unsigned long long b) {
    unsigned long long r;
    asm("mul.rn.f32x2 %0, %1, %2;" : "=l"(r) : "l"(a), "l"(b));
    return r;
}
__device__ __forceinline__ void mma8v(float* c, uint4 a, uint32_t b0, uint32_t b1) {
    asm volatile("mma.sync.aligned.m16n8k8.row.col.f32.tf32.tf32.f32 "
        "{%0,%1,%2,%3}, {%4,%5,%6,%7}, {%8,%9}, {%0,%1,%2,%3};"
        : "+f"(c[0]), "+f"(c[1]), "+f"(c[2]), "+f"(c[3])
        : "r"(a.x), "r"(a.y), "r"(a.z), "r"(a.w), "r"(b0), "r"(b1));
}

// ---- W prep: fragment order rem = ((kp*16+ntile)*32+lane)*4 + r ----
__global__ void wt_prep0(const float* __restrict__ W) {   // layer 0, symmetric fold
    int idx = blockIdx.x * 256 + threadIdx.x;
    if (idx >= NCH0 * 4096) return;
    int cl = idx >> 12, rem = idx & 4095;
    int r = rem & 3, lane = (rem >> 2) & 31, ntile = (rem >> 7) & 15, kp = rem >> 11;
    int ks = kp * 2 + (r >> 1), reg = r & 1;
    int n = ntile * 8 + (lane >> 2);
    int k = cl * 32 + ks * 8 + (lane & 3) + reg * 4;
    float v = 0.0f;
    if (k < 780) {
        int f = 0, s = 0;
        while (s + (39 - f) <= k) { s += 39 - f; ++f; }
        int g = f + (k - s);
        v = W[(size_t)(f * 39 + g) * 128 + n];
        if (g != f) v += W[(size_t)(g * 39 + f) * 128 + n];
    }
    g_wt[(size_t)cl * 4096 + rem] = tf32r(v);
}
__global__ void wt_prep(const float* __restrict__ W, int K, int chunk0, int nchunks) {
    int idx = blockIdx.x * 256 + threadIdx.x;
    if (idx >= nchunks * 4096) return;
    int cl = idx >> 12, rem = idx & 4095;
    int r = rem & 3, lane = (rem >> 2) & 31, ntile = (rem >> 7) & 15, kp = rem >> 11;
    int ks = kp * 2 + (r >> 1), reg = r & 1;
    int n = ntile * 8 + (lane >> 2);
    int k = cl * 32 + ks * 8 + (lane & 3) + reg * 4;
    float v = (k < K) ? W[(size_t)k * 128 + n] : 0.0f;
    g_wt[(size_t)(chunk0 + cl) * 4096 + rem] = tf32r(v);
}

// ---- fill slots ----
// Layer 0 (LUT, x==h):
__device__ __forceinline__ void fill_slot0(
    ulonglong2* __restrict__ adst, int tid, int icb, int c, int j,
    const unsigned long long* __restrict__ xrow, const uint32_t* __restrict__ lut)
{
    int k = icb + j * 8 + c;
    uint32_t u0 = lut[k], u1 = lut[k + 4];
    int f0 = u0 & 255, g0 = u0 >> 8;
    int f1 = u1 & 255, g1 = u1 >> 8;
    ulonglong2 o;
    o.x = mul2u(xrow[f0 * HST], xrow[g0 * HST]) + MAGIC;
    o.y = mul2u(xrow[f1 * HST], xrow[g1 * HST]) + MAGIC;
    adst[tid + 256 * j] = o;
}
// Layers 1-2 (f constant per chunk; xv preloaded; hgb = hrow + (icb&63)*HST):
__device__ __forceinline__ void fill_slot12(
    ulonglong2* __restrict__ adst, int tid, int c, int j,
    unsigned long long xv, const unsigned long long* __restrict__ hgb)
{
    int g = j * 8 + c;
    ulonglong2 o;
    o.x = mul2u(xv, hgb[g * HST]) + MAGIC;
    o.y = mul2u(xv, hgb[(g + 4) * HST]) + MAGIC;
    adst[tid + 256 * j] = o;
}

__device__ __forceinline__ void ldB4(uint4* b, const uint4* __restrict__ p) {
    #pragma unroll
    for (int nt = 0; nt < 4; ++nt) b[nt] = __ldg(p + nt * 32);
}

// Chunk body: MMA(ic), fill(ic+1) slots + B prefetch interleaved per ks.
template <int L0>
__device__ __forceinline__ void chunk_body(
    const uint4* __restrict__ ap, ulonglong2* __restrict__ an,
    float acc[4][4][4], uint4* bcur, const uint4* __restrict__ bnext,
    int dofill, int tid, int icb, int c,
    const unsigned long long* __restrict__ xrow,
    unsigned long long xv, const unsigned long long* __restrict__ hgb,
    const uint32_t* __restrict__ lut)
{
    #pragma unroll
    for (int ks = 0; ks < 4; ++ks) {
        const int kp = ks >> 1, k2 = ks & 1;
        #pragma unroll
        for (int mt = 0; mt < 4; ++mt) {
            uint4 av = ap[ks * 256 + mt * 32];
            #pragma unroll
            for (int nt = 0; nt < 4; ++nt)
                mma8v(acc[mt][nt], av,
                      k2 ? bcur[kp * 4 + nt].z : bcur[kp * 4 + nt].x,
                      k2 ? bcur[kp * 4 + nt].w : bcur[kp * 4 + nt].y);
        }
        if (dofill) {
            if (L0) fill_slot0(an, tid, icb, c, ks, xrow, lut);
            else    fill_slot12(an, tid, c, ks, xv, hgb);
        }
        if (ks == 1) ldB4(bcur, bnext);
        if (ks == 3) ldB4(bcur + 4, bnext + 512);
    }
}

__global__ void __launch_bounds__(256, 2) cin_mma_kernel(
    const float* __restrict__ x,
    const float* __restrict__ b0, const float* __restrict__ b1,
    const float* __restrict__ b2,
    float* __restrict__ out)
{
    extern __shared__ char smem[];
    float*    osum   = (float*)(smem + SM_OSUM);
    float*    bias_s = (float*)(smem + SM_BIAS);
    uint32_t* lut    = (uint32_t*)(smem + SM_LUT);
    float2*   xs2    = (float2*)(smem + SM_XS);   // [f][col], stride HST
    float2*   hs2    = (float2*)(smem + SM_HS);   // [g][col], stride HST

    const int tid = threadIdx.x, lane = tid & 31, wid = tid >> 5;
    const int pair0 = blockIdx.x * 128;
    const int wm = wid & 1, wn = wid >> 1;
    const int c = lane & 3;
    const int colid = wid * 8 + (lane >> 2);

    for (int i = tid; i < 2048; i += 256) osum[i] = 0.0f;
    for (int i = tid; i < 128 * 39; i += 256) {
        int m = i & 127, f = i >> 7, pr = pair0 + m;
        float v = x[((size_t)(pr >> 4) * 39 + f) * 16 + (pr & 15)];
        ((float*)xs2)[(f * HST + (m >> 4) * 8 + (m & 7)) * 2 + ((m >> 3) & 1)] = v;
    }
    for (int i = tid; i < 384; i += 256) {
        const float* bp = (i < 128) ? b0 : ((i < 256) ? b1 : b2);
        bias_s[i] = bp[i & 127];
    }
    for (int k = tid; k < 800; k += 256) {
        int f = 0, s = 0, g = 0;
        if (k < 780) {
            while (s + (39 - f) <= k) { s += 39 - f; ++f; }
            g = f + (k - s);
        } else f = 0;
        lut[k] = (uint32_t)f | ((uint32_t)g << 8);
    }

    float acc[4][4][4];
    #pragma unroll
    for (int a = 0; a < 4; ++a)
        #pragma unroll
        for (int b = 0; b < 4; ++b)
            #pragma unroll
            for (int cc = 0; cc < 4; ++cc) acc[a][b][cc] = 0.0f;

    ulonglong2* a0 = (ulonglong2*)(smem + SM_A0);
    ulonglong2* a1 = (ulonglong2*)(smem + SM_A1);
    const uint4* bptr = (const uint4*)g_wt + (wn * 128 + lane);
    uint4 bcur[8];
    ldB4(bcur, bptr); ldB4(bcur + 4, bptr + 512);
    int pb = 0;

    const unsigned long long* xrow = (const unsigned long long*)(xs2 + colid);

    for (int layer = 0; layer < 3; ++layer) {
        const int nck = (layer == 0) ? NCH0 : NCH12;
        const unsigned long long* hrow =
            (const unsigned long long*)(((layer == 0) ? xs2 : hs2) + colid);

        __syncthreads();                          // xs2/hs2/lut writes visible
        {   // prologue fill of chunk 0
            ulonglong2* an = pb ? a1 : a0;
            if (layer == 0) {
                #pragma unroll
                for (int j = 0; j < 4; ++j) fill_slot0(an, tid, 0, c, j, xrow, lut);
            } else {
                unsigned long long xv = xrow[0];
                #pragma unroll
                for (int j = 0; j < 4; ++j) fill_slot12(an, tid, c, j, xv, hrow);
            }
        }

        for (int ic = 0; ic < nck; ++ic) {
            __syncthreads();                      // fill(ic) visible; abuf[pb^1] free
            const uint4* ap = (pb ? (const uint4*)a1 : (const uint4*)a0) + (wm * 128 + lane);
            ulonglong2* an = pb ? a0 : a1;
            const int dofill = (ic + 1 < nck);
            const int icb = (ic + 1) * 32;
            if (layer == 0) {
                chunk_body<1>(ap, an, acc, bcur, bptr + 1024, dofill, tid,
                              icb, c, xrow, 0ull, hrow, lut);
            } else {
                unsigned long long xv = dofill ? xrow[(icb >> 6) * HST] : 0ull;
                const unsigned long long* hgb = hrow + (icb & 63) * HST;
                chunk_body<0>(ap, an, acc, bcur, bptr + 1024, dofill, tid,
                              icb, c, xrow, xv, hgb, lut);
            }
            bptr += 1024;
            pb ^= 1;
        }

        // ---- epilogue: bias + relu, h pairs for next layer, d-sum ----
        #pragma unroll
        for (int mt = 0; mt < 4; ++mt) {
            int b_loc = wm * 4 + mt;
            int hcol = (wm * 4 + mt) * 8 + (lane >> 2);
            #pragma unroll
            for (int nt = 0; nt < 4; ++nt) {
                int n = wn * 32 + nt * 8 + (lane & 3) * 2;
                float bi0 = bias_s[layer * 128 + n];
                float bi1 = bias_s[layer * 128 + n + 1];
                float v0 = fmaxf(acc[mt][nt][0] + bi0, 0.0f);
                float v1 = fmaxf(acc[mt][nt][1] + bi1, 0.0f);
                float v2 = fmaxf(acc[mt][nt][2] + bi0, 0.0f);
                float v3 = fmaxf(acc[mt][nt][3] + bi1, 0.0f);
                acc[mt][nt][0] = 0.0f; acc[mt][nt][1] = 0.0f;
                acc[mt][nt][2] = 0.0f; acc[mt][nt][3] = 0.0f;
                if (layer < 2 && n < 64) {
                    hs2[n * HST + hcol]       = make_float2(v0, v2);
                    hs2[(n + 1) * HST + hcol] = make_float2(v1, v3);
                }
                int ch = (layer == 0) ? (n >= 64 ? n - 64 : -1)
                       : (layer == 1) ? (n >= 64 ? n : -1)
                       : (128 + n);
                if (ch >= 0) {
                    atomicAdd(&osum[b_loc * 256 + ch],     v0 + v2);
                    atomicAdd(&osum[b_loc * 256 + ch + 1], v1 + v3);
                }
            }
        }
    }

    __syncthreads();
    const int bbase = blockIdx.x * 8;
    for (int i = tid; i < 2048; i += 256)
        out[(size_t)(bbase + (i >> 8)) * 256 + (i & 255)] = osum[i];
}

extern "C" void kernel_launch(void* const* d_in, const int* in_sizes, int n_in,
                              void* d_out, int out_size) {
    const float* x  = (const float*)d_in[0];
    const float* W0 = (const float*)d_in[1];
    const float* W1 = (const float*)d_in[2];
    const float* W2 = (const float*)d_in[3];
    const float* b0 = (const float*)d_in[4];
    const float* b1 = (const float*)d_in[5];
    const float* b2 = (const float*)d_in[6];
    float* out = (float*)d_out;

    wt_prep0<<<NCH0 * 16, 256>>>(W0);
    wt_prep<<<NCH12 * 16, 256>>>(W1, 2496, NCH0, NCH12);
    wt_prep<<<NCH12 * 16, 256>>>(W2, 2496, NCH0 + NCH12, NCH12);

    cudaFuncSetAttribute(cin_mma_kernel, cudaFuncAttributeMaxDynamicSharedMemorySize, SM_TOT);
    cin_mma_kernel<<<256, 256, SM_TOT>>>(x, b0, b1, b2, out);
}